// round 4
// baseline (speedup 1.0000x reference)
#include <cuda_runtime.h>
#include <cuda_fp16.h>
#include <cstdint>

#define B_    64
#define N_    2048
#define JD_   512
#define EPS_  1e-8f

// Scratch (device globals: allocation-free rule)
__device__ __half g_wh[(size_t)N_ * JD_ * 16];     // 33.5 MB fp16 W copy
__device__ __half g_xh[(size_t)B_ * N_ * 16];      // 4 MB fp16 x copy
__device__ float  g_part[(size_t)128 * B_ * JD_];  // 16.8 MB partial s per i-chunk
__device__ float  g_v[2][B_ * JD_];                // v1, (v1+v2)

__device__ __forceinline__ uint32_t packh2(float a, float b) {
    __half2 h = __floats2half2_rn(a, b);
    return *(uint32_t*)&h;
}
__device__ __forceinline__ void mma16816(float& d0, float& d1, float& d2, float& d3,
        uint32_t a0, uint32_t a1, uint32_t a2, uint32_t a3,
        uint32_t b0, uint32_t b1) {
    asm volatile(
        "mma.sync.aligned.m16n8k16.row.col.f32.f16.f16.f32 "
        "{%0,%1,%2,%3}, {%4,%5,%6,%7}, {%8,%9}, {%10,%11,%12,%13};\n"
        : "=f"(d0), "=f"(d1), "=f"(d2), "=f"(d3)
        : "r"(a0), "r"(a1), "r"(a2), "r"(a3), "r"(b0), "r"(b1),
          "f"(0.f), "f"(0.f), "f"(0.f), "f"(0.f));
}

// ---------------------------------------------------------------------------
// Pass 1 (uniform c = 1/32), fused with fp32->fp16 conversion of W and x.
// Grid 128 (i-chunks of 16), 512 thr = 16 warps: warp = (mt = wid&3 -> 16 b,
// jdr = wid>>2 -> 128 jd). Per i: u fragments via mma; acc += u; partials/32.
// mt==0 warps store W fp16; jdr==0 warps store x fp16.
// ---------------------------------------------------------------------------
__global__ __launch_bounds__(512, 1) void k_pass1(const float* __restrict__ x,
                                                  const float* __restrict__ w) {
    const int ic   = blockIdx.x;
    const int t    = threadIdx.x;
    const int wid  = t >> 5;
    const int lane = t & 31;
    const int g    = lane >> 2;
    const int tg   = lane & 3;
    const int mt   = wid & 3;
    const int jdr  = wid >> 2;
    const int jd0  = jdr * 128;
    const int row0 = mt * 16 + g;
    const int row1 = row0 + 8;

    float acc[16][4];
#pragma unroll
    for (int q = 0; q < 16; q++)
#pragma unroll
        for (int r = 0; r < 4; r++) acc[q][r] = 0.f;

    for (int k = 0; k < 16; k++) {
        const int i = ic * 16 + k;

        // A fragment from fp32 x
        const float* xp0 = x + ((size_t)row0 * N_ + i) * 16 + 2 * tg;
        const float* xp1 = x + ((size_t)row1 * N_ + i) * 16 + 2 * tg;
        float2 f0 = *(const float2*)xp0;
        float2 f1 = *(const float2*)xp1;
        float2 f2 = *(const float2*)(xp0 + 8);
        float2 f3 = *(const float2*)(xp1 + 8);
        uint32_t A0 = packh2(f0.x, f0.y);
        uint32_t A1 = packh2(f1.x, f1.y);
        uint32_t A2 = packh2(f2.x, f2.y);
        uint32_t A3 = packh2(f3.x, f3.y);

        if (jdr == 0) {   // store x fp16 (disjoint rows across mt)
            __half* xh0 = g_xh + ((size_t)row0 * N_ + i) * 16;
            __half* xh1 = g_xh + ((size_t)row1 * N_ + i) * 16;
            *(uint32_t*)(xh0 + 2 * tg)     = A0;
            *(uint32_t*)(xh1 + 2 * tg)     = A1;
            *(uint32_t*)(xh0 + 2 * tg + 8) = A2;
            *(uint32_t*)(xh1 + 2 * tg + 8) = A3;
        }

#pragma unroll
        for (int q = 0; q < 16; q++) {
            const int col = jd0 + q * 8 + g;
            const float* wp = w + ((size_t)i * JD_ + col) * 16 + 2 * tg;
            float2 w0 = *(const float2*)wp;
            float2 w1 = *(const float2*)(wp + 8);
            uint32_t Bb0 = packh2(w0.x, w0.y);
            uint32_t Bb1 = packh2(w1.x, w1.y);

            if (mt == 0) {  // store W fp16 once
                __half* wh = g_wh + ((size_t)i * JD_ + col) * 16;
                *(uint32_t*)(wh + 2 * tg)     = Bb0;
                *(uint32_t*)(wh + 2 * tg + 8) = Bb1;
            }

            float d0, d1, d2, d3;
            mma16816(d0, d1, d2, d3, A0, A1, A2, A3, Bb0, Bb1);
            acc[q][0] += d0; acc[q][1] += d1;
            acc[q][2] += d2; acc[q][3] += d3;
        }
    }

    float* pb = g_part + ((size_t)ic * B_ + row0) * JD_;
    const float cinv = 1.0f / 32.0f;
#pragma unroll
    for (int q = 0; q < 16; q++) {
        const int col = jd0 + q * 8 + 2 * tg;
        *(float2*)(pb + col)            = make_float2(acc[q][0] * cinv, acc[q][1] * cinv);
        *(float2*)(pb + 8 * JD_ + col)  = make_float2(acc[q][2] * cinv, acc[q][3] * cinv);
    }
}

// ---------------------------------------------------------------------------
// Routing pass with recomputed u (fp16 mma) + softmax weighting.
// Grid (128, 4): (i-chunk ic, b-quarter bq). 512 thr = 16 warps.
// Warp wid owns jd strip [wid*32, wid*32+32) (j = 2*wid, 2*wid+1) for the
// CTA's 16 b. Per i: mma u fragments; logit partial = u.v (v in fp32 regs);
// quad shfl-reduce; cross-warp softmax over j via smem; acc += c*u.
// ---------------------------------------------------------------------------
__global__ __launch_bounds__(512, 1) void k_rpass(int vIdx) {
    __shared__ float s_lg[16][33];
    __shared__ float s_c[16][33];

    const int ic   = blockIdx.x;
    const int bq   = blockIdx.y;
    const int t    = threadIdx.x;
    const int wid  = t >> 5;
    const int lane = t & 31;
    const int g    = lane >> 2;
    const int tg   = lane & 3;
    const int jd0  = wid * 32;
    const int row0 = bq * 16 + g;    // global b
    const int row1 = row0 + 8;

    // v (i-invariant) into registers: per q the 2 cols x 2 rows this lane owns
    float vv[4][4];
#pragma unroll
    for (int q = 0; q < 4; q++) {
        const int col = jd0 + q * 8 + 2 * tg;
        float2 a = *(const float2*)&g_v[vIdx][row0 * JD_ + col];
        float2 b = *(const float2*)&g_v[vIdx][row1 * JD_ + col];
        vv[q][0] = a.x; vv[q][1] = a.y; vv[q][2] = b.x; vv[q][3] = b.y;
    }

    float acc[4][4];
#pragma unroll
    for (int q = 0; q < 4; q++)
#pragma unroll
        for (int r = 0; r < 4; r++) acc[q][r] = 0.f;

    for (int k = 0; k < 16; k++) {
        const int i = ic * 16 + k;

        const __half* xh0 = g_xh + ((size_t)row0 * N_ + i) * 16;
        const __half* xh1 = g_xh + ((size_t)row1 * N_ + i) * 16;
        uint32_t A0 = *(const uint32_t*)(xh0 + 2 * tg);
        uint32_t A1 = *(const uint32_t*)(xh1 + 2 * tg);
        uint32_t A2 = *(const uint32_t*)(xh0 + 2 * tg + 8);
        uint32_t A3 = *(const uint32_t*)(xh1 + 2 * tg + 8);

        float u[4][4];
        float lgA[2] = {0.f, 0.f}, lgB[2] = {0.f, 0.f};
#pragma unroll
        for (int q = 0; q < 4; q++) {
            const int col = jd0 + q * 8 + g;
            const __half* wh = g_wh + ((size_t)i * JD_ + col) * 16;
            uint32_t Bb0 = *(const uint32_t*)(wh + 2 * tg);
            uint32_t Bb1 = *(const uint32_t*)(wh + 2 * tg + 8);

            mma16816(u[q][0], u[q][1], u[q][2], u[q][3], A0, A1, A2, A3, Bb0, Bb1);
            lgA[q >> 1] += u[q][0] * vv[q][0] + u[q][1] * vv[q][1];
            lgB[q >> 1] += u[q][2] * vv[q][2] + u[q][3] * vv[q][3];
        }

        // complete logit over d: reduce across the 4 tg lanes of the quad
#pragma unroll
        for (int jj = 0; jj < 2; jj++) {
            lgA[jj] += __shfl_xor_sync(0xffffffffu, lgA[jj], 1);
            lgA[jj] += __shfl_xor_sync(0xffffffffu, lgA[jj], 2);
            lgB[jj] += __shfl_xor_sync(0xffffffffu, lgB[jj], 1);
            lgB[jj] += __shfl_xor_sync(0xffffffffu, lgB[jj], 2);
        }
        if (tg == 0) {
            s_lg[g][2 * wid]         = lgA[0];
            s_lg[g][2 * wid + 1]     = lgA[1];
            s_lg[g + 8][2 * wid]     = lgB[0];
            s_lg[g + 8][2 * wid + 1] = lgB[1];
        }
        __syncthreads();

        // softmax over 32 j: warp wid handles local b = wid, lane = j
        {
            float l = s_lg[wid][lane];
            float m = l;
#pragma unroll
            for (int o = 16; o > 0; o >>= 1)
                m = fmaxf(m, __shfl_xor_sync(0xffffffffu, m, o));
            float ex = __expf(l - m);
            float sum = ex;
#pragma unroll
            for (int o = 16; o > 0; o >>= 1)
                sum += __shfl_xor_sync(0xffffffffu, sum, o);
            s_c[wid][lane] = ex / sum;
        }
        __syncthreads();

        float cA0 = s_c[g][2 * wid],     cA1 = s_c[g][2 * wid + 1];
        float cB0 = s_c[g + 8][2 * wid], cB1 = s_c[g + 8][2 * wid + 1];

#pragma unroll
        for (int q = 0; q < 4; q++) {
            const float ca = (q >> 1) ? cA1 : cA0;
            const float cb = (q >> 1) ? cB1 : cB0;
            acc[q][0] += ca * u[q][0]; acc[q][1] += ca * u[q][1];
            acc[q][2] += cb * u[q][2]; acc[q][3] += cb * u[q][3];
        }
    }

    float* pb = g_part + ((size_t)ic * B_ + row0) * JD_;
#pragma unroll
    for (int q = 0; q < 4; q++) {
        const int col = jd0 + q * 8 + 2 * tg;
        *(float2*)(pb + col)           = make_float2(acc[q][0], acc[q][1]);
        *(float2*)(pb + 8 * JD_ + col) = make_float2(acc[q][2], acc[q][3]);
    }
}

// ---------------------------------------------------------------------------
// Reduce partials over 128 i-chunks, then squash.
// mode 0: g_v[0] = squash_J(s)                 (v1)
// mode 1: g_v[1] = squash_J(s) + g_v[0]        (v1 + v2, additive logits)
// mode 2: out    = squash_D(s)                 (final output)
// ---------------------------------------------------------------------------
__global__ void k_red_squash(int mode, float* __restrict__ out) {
    const int b = blockIdx.x;
    const int t = threadIdx.x;     // t = j*16 + d
    const float* p = g_part + (size_t)b * JD_ + t;
    float s = 0.f;
#pragma unroll 16
    for (int ic = 0; ic < 128; ic++)
        s += p[(size_t)ic * B_ * JD_];

    if (mode == 2) {
        float q = s * s;
#pragma unroll
        for (int o = 1; o < 16; o <<= 1)      // 16 consecutive lanes = same j
            q += __shfl_xor_sync(0xffffffffu, q, o);
        out[b * JD_ + t] = s * (q / (1.f + q)) * rsqrtf(q + EPS_);
        return;
    }

    __shared__ float sq[16];
    if (t < 16) sq[t] = 0.f;
    __syncthreads();
    atomicAdd(&sq[t & 15], s * s);
    __syncthreads();
    float q = sq[t & 15];
    float v = s * (q / (1.f + q)) * rsqrtf(q + EPS_);
    if (mode == 0) g_v[0][b * JD_ + t] = v;
    else           g_v[1][b * JD_ + t] = v + g_v[0][b * JD_ + t];
}

// ---------------------------------------------------------------------------
extern "C" void kernel_launch(void* const* d_in, const int* in_sizes, int n_in,
                              void* d_out, int out_size) {
    const float* x = (const float*)d_in[0];
    const float* w = (const float*)d_in[1];
    if (in_sizes[0] != B_ * N_ * 16) {       // defensive input-order check
        x = (const float*)d_in[1];
        w = (const float*)d_in[0];
    }

    k_pass1<<<128, 512>>>(x, w);                 // s1 partials + fp16 W/x copies
    k_red_squash<<<B_, JD_>>>(0, nullptr);       // v1 = squash_J(s1)
    dim3 pg(128, 4);
    k_rpass<<<pg, 512>>>(0);                     // iter 2: c = softmax(u.v1) -> s2
    k_red_squash<<<B_, JD_>>>(1, nullptr);       // vsum = squash_J(s2) + v1
    k_rpass<<<pg, 512>>>(1);                     // final: c = softmax(u.vsum) -> s3
    k_red_squash<<<B_, JD_>>>(2, (float*)d_out); // out = squash_D(s3)
}

// round 5
// speedup vs baseline: 1.4071x; 1.4071x over previous
#include <cuda_runtime.h>
#include <cuda_fp16.h>
#include <cstdint>

#define B_    64
#define N_    2048
#define JD_   512
#define EPS_  1e-8f
#define SROW  136   // smem row stride in halves (272 B): conflict-free frag stores

// Scratch (device globals: allocation-free rule)
__device__ __half g_u[(size_t)B_ * N_ * JD_];        // 134 MB u[b][i][jd] fp16
__device__ float  g_part1[(size_t)128 * B_ * JD_];   // s1 partials (128 chunks)
__device__ float  g_part2[(size_t)16 * B_ * JD_];    // s2/s3 partials (16 chunks)
__device__ float  g_s1[B_ * JD_];                    // reduced s1
__device__ float  g_v[2][B_ * JD_];                  // v1, (v1+v2)

__device__ __forceinline__ uint32_t packh2(float a, float b) {
    __half2 h = __floats2half2_rn(a, b);
    return *(uint32_t*)&h;
}
__device__ __forceinline__ void mma16816(float& d0, float& d1, float& d2, float& d3,
        uint32_t a0, uint32_t a1, uint32_t a2, uint32_t a3,
        uint32_t b0, uint32_t b1) {
    asm volatile(
        "mma.sync.aligned.m16n8k16.row.col.f32.f16.f16.f32 "
        "{%0,%1,%2,%3}, {%4,%5,%6,%7}, {%8,%9}, {%10,%11,%12,%13};\n"
        : "=f"(d0), "=f"(d1), "=f"(d2), "=f"(d3)
        : "r"(a0), "r"(a1), "r"(a2), "r"(a3), "r"(b0), "r"(b1),
          "f"(0.f), "f"(0.f), "f"(0.f), "f"(0.f));
}

// ---------------------------------------------------------------------------
// k_u: tensor-core einsum -> u (fp16, coalesced via smem transpose) + fused
// pass 1 (uniform c = 1/32) partials.
// Grid 128 (16 i each), 512 thr = 16 warps; warp = (mt: 16 b) x (jdr: 128 jd).
// Fragments staged in smem (row stride 272 B -> conflict-free STS.32), then
// copied out as 256 B coalesced rows: u[b][i][jd].
// ---------------------------------------------------------------------------
__global__ __launch_bounds__(512, 1) void k_u(const float* __restrict__ x,
                                              const float* __restrict__ w) {
    extern __shared__ __half us[];       // 16 warps * 16 rows * SROW halves
    const int ic   = blockIdx.x;
    const int t    = threadIdx.x;
    const int wid  = t >> 5;
    const int lane = t & 31;
    const int g    = lane >> 2;
    const int tg   = lane & 3;
    const int mt   = wid & 3;
    const int jdr  = wid >> 2;
    const int jd0  = jdr * 128;
    const int row0 = mt * 16 + g;
    const int row1 = row0 + 8;
    __half* usw = us + wid * 16 * SROW;  // this warp's 16x128 tile

    float acc[16][4];
#pragma unroll
    for (int q = 0; q < 16; q++)
#pragma unroll
        for (int r = 0; r < 4; r++) acc[q][r] = 0.f;

    for (int k = 0; k < 16; k++) {
        const int i = ic * 16 + k;

        // A fragment from fp32 x
        const float* xp0 = x + ((size_t)row0 * N_ + i) * 16 + 2 * tg;
        const float* xp1 = x + ((size_t)row1 * N_ + i) * 16 + 2 * tg;
        float2 f0 = *(const float2*)xp0;
        float2 f1 = *(const float2*)xp1;
        float2 f2 = *(const float2*)(xp0 + 8);
        float2 f3 = *(const float2*)(xp1 + 8);
        uint32_t A0 = packh2(f0.x, f0.y);
        uint32_t A1 = packh2(f1.x, f1.y);
        uint32_t A2 = packh2(f2.x, f2.y);
        uint32_t A3 = packh2(f3.x, f3.y);

#pragma unroll
        for (int q = 0; q < 16; q++) {
            const int col = jd0 + q * 8 + g;
            const float* wp = w + ((size_t)i * JD_ + col) * 16 + 2 * tg;
            float2 w0 = *(const float2*)wp;
            float2 w1 = *(const float2*)(wp + 8);
            uint32_t Bb0 = packh2(w0.x, w0.y);
            uint32_t Bb1 = packh2(w1.x, w1.y);

            float d0, d1, d2, d3;
            mma16816(d0, d1, d2, d3, A0, A1, A2, A3, Bb0, Bb1);
            acc[q][0] += d0; acc[q][1] += d1;
            acc[q][2] += d2; acc[q][3] += d3;

            // stage fragments: row-local col q*8+2tg, rows g / g+8
            *(uint32_t*)(usw + g * SROW        + q * 8 + 2 * tg) = packh2(d0, d1);
            *(uint32_t*)(usw + (g + 8) * SROW  + q * 8 + 2 * tg) = packh2(d2, d3);
        }
        __syncwarp();

        // coalesced copy-out: 16 rows x 256 B -> u[b][i][jd0..jd0+128)
#pragma unroll
        for (int it = 0; it < 8; it++) {
            const int r   = it * 2 + (lane >> 4);
            const int off = lane & 15;
            uint4 v = *(const uint4*)(usw + r * SROW + off * 8);
            *(uint4*)(g_u + ((size_t)(mt * 16 + r) * N_ + i) * JD_ + jd0 + off * 8) = v;
        }
        __syncwarp();
    }

    // s1 partials: g_part1[ic][b][jd], scaled by 1/32
    float* pb = g_part1 + ((size_t)ic * B_ + row0) * JD_;
    const float cinv = 1.0f / 32.0f;
#pragma unroll
    for (int q = 0; q < 16; q++) {
        const int col = jd0 + q * 8 + 2 * tg;
        *(float2*)(pb + col)           = make_float2(acc[q][0] * cinv, acc[q][1] * cinv);
        *(float2*)(pb + 8 * JD_ + col) = make_float2(acc[q][2] * cinv, acc[q][3] * cinv);
    }
}

// ---------------------------------------------------------------------------
// Flat reduce of s1 partials over 128 chunks (high-parallelism).
// ---------------------------------------------------------------------------
__global__ void k_red1() {
    const int idx = blockIdx.x * 128 + threadIdx.x;   // 256 CTAs x 128 = 32768
    const float* p = g_part1 + idx;
    float s = 0.f;
#pragma unroll 16
    for (int ic = 0; ic < 128; ic++)
        s += p[(size_t)ic * B_ * JD_];
    g_s1[idx] = s;
}

// ---------------------------------------------------------------------------
// v1 = squash_J(g_s1)
// ---------------------------------------------------------------------------
__global__ void k_squash1() {
    const int b = blockIdx.x;
    const int t = threadIdx.x;     // t = j*16 + d
    float s = g_s1[b * JD_ + t];
    __shared__ float sq[16];
    if (t < 16) sq[t] = 0.f;
    __syncthreads();
    atomicAdd(&sq[t & 15], s * s);
    __syncthreads();
    float q = sq[t & 15];
    g_v[0][b * JD_ + t] = s * (q / (1.f + q)) * rsqrtf(q + EPS_);
}

// ---------------------------------------------------------------------------
// Routing sweep over fp16 u, 2-way i ILP. Grid (16, 64), 256 thr = 8 warps,
// warp handles 16 i (2 at a time), lane = j. Writes g_part2[ic][b][jd].
// ---------------------------------------------------------------------------
__global__ __launch_bounds__(256) void k_pass(int vIdx) {
    const int b    = blockIdx.y;
    const int ic   = blockIdx.x;
    const int t    = threadIdx.x;
    const int warp = t >> 5;
    const int j    = t & 31;

    __shared__ float vs[JD_];
    __shared__ float ss[8][JD_];

    for (int idx = t; idx < JD_; idx += 256)
        vs[idx] = g_v[vIdx][b * JD_ + idx];
    __syncthreads();

    float vj[16];
#pragma unroll
    for (int d = 0; d < 16; d++) vj[d] = vs[j * 16 + d];

    float acc[16];
#pragma unroll
    for (int d = 0; d < 16; d++) acc[d] = 0.f;

    const int ibase = ic * 128 + warp * 16;
#pragma unroll 2
    for (int k = 0; k < 16; k += 2) {
        const uint4* up = (const uint4*)(g_u + ((size_t)b * N_ + ibase + k) * JD_) + j * 2;
        uint4 p0 = __ldcs(up);        // i0 lo
        uint4 p1 = __ldcs(up + 1);    // i0 hi
        uint4 p2 = __ldcs(up + 64);   // i1 lo   (next i row = 512 halves = 64 uint4)
        uint4 p3 = __ldcs(up + 65);   // i1 hi

        // logits (unpack half2 on the fly)
        float bl0 = 0.f, bl1 = 0.f;
        {
            const __half2* a0 = (const __half2*)&p0;
            const __half2* a1 = (const __half2*)&p1;
            const __half2* c0 = (const __half2*)&p2;
            const __half2* c1 = (const __half2*)&p3;
#pragma unroll
            for (int q = 0; q < 4; q++) {
                float2 u0 = __half22float2(a0[q]);
                float2 u1 = __half22float2(a1[q]);
                float2 w0 = __half22float2(c0[q]);
                float2 w1 = __half22float2(c1[q]);
                bl0 += u0.x * vj[2*q] + u0.y * vj[2*q+1]
                     + u1.x * vj[8+2*q] + u1.y * vj[8+2*q+1];
                bl1 += w0.x * vj[2*q] + w0.y * vj[2*q+1]
                     + w1.x * vj[8+2*q] + w1.y * vj[8+2*q+1];
            }
        }

        // dual softmax over the 32 j-lanes
        float m0 = bl0, m1 = bl1;
#pragma unroll
        for (int o = 16; o > 0; o >>= 1) {
            m0 = fmaxf(m0, __shfl_xor_sync(0xffffffffu, m0, o));
            m1 = fmaxf(m1, __shfl_xor_sync(0xffffffffu, m1, o));
        }
        float e0 = __expf(bl0 - m0), e1 = __expf(bl1 - m1);
        float s0 = e0, s1 = e1;
#pragma unroll
        for (int o = 16; o > 0; o >>= 1) {
            s0 += __shfl_xor_sync(0xffffffffu, s0, o);
            s1 += __shfl_xor_sync(0xffffffffu, s1, o);
        }
        const float c0f = e0 / s0, c1f = e1 / s1;

        // acc += c * u (second unpack)
        {
            const __half2* a0 = (const __half2*)&p0;
            const __half2* a1 = (const __half2*)&p1;
            const __half2* c0 = (const __half2*)&p2;
            const __half2* c1 = (const __half2*)&p3;
#pragma unroll
            for (int q = 0; q < 4; q++) {
                float2 u0 = __half22float2(a0[q]);
                float2 u1 = __half22float2(a1[q]);
                float2 w0 = __half22float2(c0[q]);
                float2 w1 = __half22float2(c1[q]);
                acc[2*q]     += c0f * u0.x + c1f * w0.x;
                acc[2*q+1]   += c0f * u0.y + c1f * w0.y;
                acc[8+2*q]   += c0f * u1.x + c1f * w1.x;
                acc[8+2*q+1] += c0f * u1.y + c1f * w1.y;
            }
        }
    }

#pragma unroll
    for (int d = 0; d < 16; d++) ss[warp][d * 32 + j] = acc[d];
    __syncthreads();

    for (int idx = t; idx < JD_; idx += 256) {
        int d = idx >> 5, jj = idx & 31;
        float r = 0.f;
#pragma unroll
        for (int wi = 0; wi < 8; wi++) r += ss[wi][idx];
        g_part2[((size_t)ic * B_ + b) * JD_ + jj * 16 + d] = r;
    }
}

// ---------------------------------------------------------------------------
// Reduce g_part2 over 16 chunks, then squash.
// mode 1: g_v[1] = squash_J(s) + g_v[0]   (v1 + v2, additive logits)
// mode 2: out    = squash_D(s)
// ---------------------------------------------------------------------------
__global__ void k_squash2(int mode, float* __restrict__ out) {
    const int b = blockIdx.x;
    const int t = threadIdx.x;     // t = j*16 + d
    const float* p = g_part2 + (size_t)b * JD_ + t;
    float s = 0.f;
#pragma unroll
    for (int ic = 0; ic < 16; ic++)
        s += p[(size_t)ic * B_ * JD_];

    if (mode == 2) {
        float q = s * s;
#pragma unroll
        for (int o = 1; o < 16; o <<= 1)
            q += __shfl_xor_sync(0xffffffffu, q, o);
        out[b * JD_ + t] = s * (q / (1.f + q)) * rsqrtf(q + EPS_);
        return;
    }

    __shared__ float sq[16];
    if (t < 16) sq[t] = 0.f;
    __syncthreads();
    atomicAdd(&sq[t & 15], s * s);
    __syncthreads();
    float q = sq[t & 15];
    float v = s * (q / (1.f + q)) * rsqrtf(q + EPS_);
    g_v[1][b * JD_ + t] = v + g_v[0][b * JD_ + t];
}

// ---------------------------------------------------------------------------
extern "C" void kernel_launch(void* const* d_in, const int* in_sizes, int n_in,
                              void* d_out, int out_size) {
    const float* x = (const float*)d_in[0];
    const float* w = (const float*)d_in[1];
    if (in_sizes[0] != B_ * N_ * 16) {       // defensive input-order check
        x = (const float*)d_in[1];
        w = (const float*)d_in[0];
    }

    const int smemB = 16 * 16 * SROW * 2;    // 69632 B
    cudaFuncSetAttribute(k_u, cudaFuncAttributeMaxDynamicSharedMemorySize, smemB);

    k_u<<<128, 512, smemB>>>(x, w);              // u fp16 + s1 partials
    k_red1<<<256, 128>>>();                      // s1 = reduce(partials)
    k_squash1<<<B_, JD_>>>();                    // v1 = squash_J(s1)
    dim3 pg(16, B_);
    k_pass<<<pg, 256>>>(0);                      // iter 2: softmax(u.v1) -> s2
    k_squash2<<<B_, JD_>>>(1, nullptr);          // vsum = squash_J(s2) + v1
    k_pass<<<pg, 256>>>(1);                      // final: softmax(u.vsum) -> s3
    k_squash2<<<B_, JD_>>>(2, (float*)d_out);    // out = squash_D(s3)
}